// round 9
// baseline (speedup 1.0000x reference)
#include <cuda_runtime.h>
#include <cuda_bf16.h>
#include <math.h>

// Problem constants (fixed shapes per reference)
#define NN    100000      // total nodes
#define BB    50          // graphs
#define NPG   2000        // nodes per graph
#define FF    64          // input features
#define HH    64          // hidden
#define EE    1600000     // edges
#define EPG   (EE / BB)   // 32000 edges per graph (graph-contiguous by construction)
#define NSEG  4
#define SEGE  (EPG / NSEG)   // 8000 edges per segment
#define NBANDS 3
#define NZF   2400000     // framelet nnz
#define NZPG  (NZF / BB)  // 48000 nz per graph (graph-contiguous)
#define NCC   10          // classes

// ---------------- static scratch (no allocation allowed) ----------------
__device__ __align__(256) float g_bufA[(size_t)NN * HH];
__device__ __align__(256) float g_bufB[(size_t)NN * HH];
__device__ __align__(256) float g_dinv[NN];
__device__ __align__(256) int   g_cnt[NN];
__device__ __align__(256) int   g_off[NN];
__device__ __align__(256) int   g_segoff[NSEG][NN];
__device__ __align__(256) int   g_col[EE];
__device__ __align__(256) float g_w[(size_t)NN * NBANDS];
__device__ __align__(256) float g_xp[BB * NBANDS * HH];

// ---------------- streams/events for intra-graph parallelism ----------------
struct StreamPack {
    cudaStream_t sB = nullptr, sC = nullptr;
    cudaEvent_t  ev0 = nullptr, evD = nullptr, evB = nullptr, evC = nullptr;
    bool ok = false;
    StreamPack() {
        if (cudaStreamCreateWithFlags(&sB, cudaStreamNonBlocking) != cudaSuccess) return;
        if (cudaStreamCreateWithFlags(&sC, cudaStreamNonBlocking) != cudaSuccess) return;
        if (cudaEventCreateWithFlags(&ev0, cudaEventDisableTiming) != cudaSuccess) return;
        if (cudaEventCreateWithFlags(&evD, cudaEventDisableTiming) != cudaSuccess) return;
        if (cudaEventCreateWithFlags(&evB, cudaEventDisableTiming) != cudaSuccess) return;
        if (cudaEventCreateWithFlags(&evC, cudaEventDisableTiming) != cudaSuccess) return;
        ok = true;
    }
};
static StreamPack g_sp;

// ---------------- build1: per-graph segmented hist + scan --------------------
// One block per graph. Produces g_cnt, g_off, g_dinv, and per-(segment,node)
// scatter start offsets g_segoff.
__global__ void __launch_bounds__(1024, 1)
build1_kernel(const int* __restrict__ erow) {
    __shared__ int hcnt[NSEG][NPG];    // 32 KB
    __shared__ int warp_part[32];
    __shared__ int warp_off[32];
    int g = blockIdx.x;
    int t = threadIdx.x;
    int lane = t & 31, warp = t >> 5;
    int node0 = g * NPG;
    int ebase = g * EPG;

    for (int i = t; i < NSEG * NPG; i += 1024) ((int*)hcnt)[i] = 0;
    __syncthreads();

    // segmented histogram (smem atomics; 4x fewer conflicts than single hist)
    for (int i = t; i < EPG; i += 1024) {
        int seg = i / SEGE;
        atomicAdd(&hcnt[seg][__ldg(&erow[ebase + i]) - node0], 1);
    }
    __syncthreads();

    // block scan of 2000 node totals: threads 0..999 handle nodes {2t, 2t+1}
    int c0[NSEG], c1[NSEG];
    int tot0 = 0, tot1 = 0, s = 0;
    if (t < NPG / 2) {
#pragma unroll
        for (int q = 0; q < NSEG; q++) {
            c0[q] = hcnt[q][2 * t];
            c1[q] = hcnt[q][2 * t + 1];
            tot0 += c0[q];
            tot1 += c1[q];
        }
        s = tot0 + tot1;
    }
    int incl = s;
    for (int d = 1; d < 32; d <<= 1) {
        int u = __shfl_up_sync(0xffffffff, incl, d);
        if (lane >= d) incl += u;
    }
    if (lane == 31) warp_part[warp] = incl;
    __syncthreads();
    if (t < 32) {
        int x = warp_part[t];
        int wincl = x;
        for (int d = 1; d < 32; d <<= 1) {
            int u = __shfl_up_sync(0xffffffff, wincl, d);
            if (t >= d) wincl += u;
        }
        warp_off[t] = wincl - x;
    }
    __syncthreads();
    if (t < NPG / 2) {
        int excl = (incl - s) + warp_off[warp];     // within-graph offset
        int base0 = ebase + excl;                   // node 2t global offset
        int base1 = base0 + tot0;                   // node 2t+1 global offset
        int r = node0 + 2 * t;
        g_off[r]     = base0;
        g_off[r + 1] = base1;
        g_cnt[r]     = tot0;
        g_cnt[r + 1] = tot1;
        g_dinv[r]     = rsqrtf((float)(tot0 + 1));
        g_dinv[r + 1] = rsqrtf((float)(tot1 + 1));
        int run0 = base0, run1 = base1;
#pragma unroll
        for (int q = 0; q < NSEG; q++) {
            g_segoff[q][r]     = run0;  run0 += c0[q];
            g_segoff[q][r + 1] = run1;  run1 += c1[q];
        }
    }
}

// ---------------- build2: segmented scatter (4 blocks per graph) -------------
__global__ void __launch_bounds__(1024, 2)
build2_kernel(const int* __restrict__ erow, const int* __restrict__ ecol) {
    __shared__ int cur[NPG];         // 8 KB
    int g   = blockIdx.x / NSEG;
    int seg = blockIdx.x % NSEG;
    int t = threadIdx.x;
    int node0 = g * NPG;
    int ebase = g * EPG + seg * SEGE;

    for (int i = t; i < NPG; i += 1024) cur[i] = g_segoff[seg][node0 + i];
    __syncthreads();

    for (int i = t; i < SEGE; i += 1024) {
        int r = __ldg(&erow[ebase + i]) - node0;
        int c = __ldg(&ecol[ebase + i]);
        int pos = atomicAdd(&cur[r], 1);
        g_col[pos] = c;
    }
}

// ---------------- GEMM: Y[r] = dinv[r] * (X[r] @ W) ----------------
__global__ void gemm64_kernel(const float* __restrict__ X, const float* __restrict__ W,
                              float* __restrict__ Y, int M) {
    __shared__ float Ws[64 * 64];
    __shared__ float Xs[64][65];
    int t = threadIdx.x;
    int row0 = blockIdx.x * 64;
    int rows = min(64, M - row0);

    for (int i = t; i < 1024; i += 256)
        ((float4*)Ws)[i] = ((const float4*)W)[i];
    for (int i = t; i < rows * 64; i += 256) {
        int r = i >> 6, c = i & 63;
        Xs[r][c] = X[(size_t)(row0 + r) * 64 + c];
    }
    __syncthreads();

    int r = t & 63;
    int cg = t >> 6;            // 0..3 -> 16 columns each
    if (r < rows) {
        float acc[16];
#pragma unroll
        for (int j = 0; j < 16; j++) acc[j] = 0.0f;
#pragma unroll 8
        for (int k = 0; k < 64; k++) {
            float a = Xs[r][k];
            const float4* wr = (const float4*)(Ws + k * 64 + cg * 16);
#pragma unroll
            for (int j = 0; j < 4; j++) {
                float4 w = wr[j];
                acc[4 * j + 0] += a * w.x;
                acc[4 * j + 1] += a * w.y;
                acc[4 * j + 2] += a * w.z;
                acc[4 * j + 3] += a * w.w;
            }
        }
        float dv = g_dinv[row0 + r];
        float4* yp = (float4*)(Y + (size_t)(row0 + r) * 64 + cg * 16);
#pragma unroll
        for (int j = 0; j < 4; j++)
            yp[j] = make_float4(dv * acc[4 * j], dv * acc[4 * j + 1],
                                dv * acc[4 * j + 2], dv * acc[4 * j + 3]);
    }
}

// ---------------- GCN aggregation (gather over CSR) + bias + relu ----------------
// hin rows are pre-scaled by dinv.  out[r] = relu(dinv[r]*(sum_c h'[c] + h'[r]) + b)
// warp per row, two 16-lane groups, float4 lanes (256B row per neighbor), x2 unroll.
__global__ void agg_kernel(const float* __restrict__ hin, float* __restrict__ hout,
                           const float* __restrict__ bias) {
    int warp = (blockIdx.x * blockDim.x + threadIdx.x) >> 5;
    if (warp >= NN) return;
    int lane = threadIdx.x & 31;
    int grp  = lane >> 4;        // 0 or 1
    int fo   = lane & 15;        // float4 slot within row
    int row = warp;
    int off = g_off[row];
    int cnt = g_cnt[row];
    float4 a0 = make_float4(0.f, 0.f, 0.f, 0.f);
    float4 a1 = make_float4(0.f, 0.f, 0.f, 0.f);
    int k = grp;
    for (; k + 2 < cnt; k += 4) {
        int c0 = __ldg(&g_col[off + k]);
        int c1 = __ldg(&g_col[off + k + 2]);
        float4 v0 = *(const float4*)(hin + (size_t)c0 * 64 + fo * 4);
        float4 v1 = *(const float4*)(hin + (size_t)c1 * 64 + fo * 4);
        a0.x += v0.x; a0.y += v0.y; a0.z += v0.z; a0.w += v0.w;
        a1.x += v1.x; a1.y += v1.y; a1.z += v1.z; a1.w += v1.w;
    }
    for (; k < cnt; k += 2) {
        int c = __ldg(&g_col[off + k]);
        float4 v = *(const float4*)(hin + (size_t)c * 64 + fo * 4);
        a0.x += v.x; a0.y += v.y; a0.z += v.z; a0.w += v.w;
    }
    if (grp == 0) {  // self loop, added once
        float4 v = *(const float4*)(hin + (size_t)row * 64 + fo * 4);
        a0.x += v.x; a0.y += v.y; a0.z += v.z; a0.w += v.w;
    }
    a0.x += a1.x; a0.y += a1.y; a0.z += a1.z; a0.w += a1.w;
    a0.x += __shfl_down_sync(0xffffffff, a0.x, 16);
    a0.y += __shfl_down_sync(0xffffffff, a0.y, 16);
    a0.z += __shfl_down_sync(0xffffffff, a0.z, 16);
    a0.w += __shfl_down_sync(0xffffffff, a0.w, 16);
    if (grp == 0) {
        float di = g_dinv[row];
        float4 b = *(const float4*)(bias + fo * 4);
        float4 o;
        o.x = fmaxf(di * a0.x + b.x, 0.f);
        o.y = fmaxf(di * a0.y + b.y, 0.f);
        o.z = fmaxf(di * a0.z + b.z, 0.f);
        o.w = fmaxf(di * a0.w + b.w, 0.f);
        *(float4*)(hout + (size_t)row * 64 + fo * 4) = o;
    }
}

// ---------------- framelet node-band weights (independent of GCN path) -------
__global__ void __launch_bounds__(1024, 1)
frame_kernel(const int* __restrict__ frow, const int* __restrict__ fcol,
             const float* __restrict__ fval, const int* __restrict__ dindex) {
    __shared__ float ws[NPG * NBANDS];   // 24 KB
    int g = blockIdx.x;
    int t = threadIdx.x;
    int node0 = g * NPG;
    for (int i = t; i < NPG * NBANDS; i += 1024) ws[i] = 0.0f;
    __syncthreads();
    int base = g * NZPG;
    for (int i = t; i < NZPG; i += 1024) {
        int k = base + i;
        int band = __ldg(&dindex[frow[k]]);
        int c = fcol[k] - node0;
        atomicAdd(&ws[c * NBANDS + band], fval[k]);
    }
    __syncthreads();
    float* dst = g_w + (size_t)g * NPG * NBANDS;
    for (int i = t; i < (NPG * NBANDS) / 4; i += 1024)
        ((float4*)dst)[i] = ((const float4*)ws)[i];
}

// ---------------- pool partial: 4 chunks/graph, atomic into g_xp -------------
#define CHUNK (NPG / 4)    // 500 nodes
__global__ void __launch_bounds__(192, 4)
pool_partial_kernel(const float* __restrict__ h) {
    __shared__ float ws[CHUNK * NBANDS];   // 6 KB
    int g  = blockIdx.x >> 2;
    int ch = blockIdx.x & 3;
    int t  = threadIdx.x;          // 0..191
    int node0 = g * NPG + ch * CHUNK;

    const float* src = g_w + (size_t)node0 * NBANDS;
    for (int i = t; i < CHUNK * NBANDS; i += 192) ws[i] = src[i];
    __syncthreads();

    int band = t / 64, f = t % 64;
    float acc = 0.0f;
#pragma unroll 4
    for (int nd = 0; nd < CHUNK; nd++)
        acc += ws[nd * NBANDS + band] * __ldg(&h[(size_t)(node0 + nd) * 64 + f]);
    atomicAdd(&g_xp[g * (NBANDS * HH) + band * 64 + f], acc);
}

// ---------------- MLP head ----------------
__global__ void head_kernel(const float* __restrict__ fcW1, const float* __restrict__ fcb1,
                            const float* __restrict__ fcW2, const float* __restrict__ fcb2,
                            float* __restrict__ out) {
    __shared__ float xs[NBANDS * HH];
    __shared__ float hid[HH];
    int g = blockIdx.x;
    int t = threadIdx.x;                // 64 threads
    for (int i = t; i < NBANDS * HH; i += 64)
        xs[i] = g_xp[g * (NBANDS * HH) + i];
    __syncthreads();
    float acc = fcb1[t];
#pragma unroll 8
    for (int k = 0; k < NBANDS * HH; k++)
        acc += xs[k] * fcW1[k * HH + t];
    hid[t] = fmaxf(acc, 0.0f);
    __syncthreads();
    if (t < NCC) {
        float o = fcb2[t];
#pragma unroll 8
        for (int k = 0; k < HH; k++)
            o += hid[k] * fcW2[k * NCC + t];
        out[g * NCC + t] = o;
    }
}

// ---------------- launch ----------------
extern "C" void kernel_launch(void* const* d_in, const int* in_sizes, int n_in,
                              void* d_out, int out_size) {
    const float* x         = (const float*)d_in[0];
    const int*   ei        = (const int*)  d_in[1];   // [2, E]: rows then cols
    const int*   frow      = (const int*)  d_in[3];
    const int*   fcol      = (const int*)  d_in[4];
    const float* fval      = (const float*)d_in[5];
    const int*   dindex    = (const int*)  d_in[6];
    const float* W1        = (const float*)d_in[8];
    const float* b1        = (const float*)d_in[9];
    const float* W2        = (const float*)d_in[10];
    const float* b2        = (const float*)d_in[11];
    const float* fcW1      = (const float*)d_in[12];
    const float* fcb1      = (const float*)d_in[13];
    const float* fcW2      = (const float*)d_in[14];
    const float* fcb2      = (const float*)d_in[15];
    float* out = (float*)d_out;

    const int* erow = ei;
    const int* ecol = ei + EE;

    float* bufA; cudaGetSymbolAddress((void**)&bufA, g_bufA);
    float* bufB; cudaGetSymbolAddress((void**)&bufB, g_bufB);
    float* xp;   cudaGetSymbolAddress((void**)&xp,   g_xp);

    bool par = g_sp.ok;

    if (par) {
        // framelet weights are input-only: run from t=0 on sC
        cudaEventRecord(g_sp.ev0, 0);
        cudaStreamWaitEvent(g_sp.sC, g_sp.ev0, 0);
        frame_kernel<<<BB, 1024, 0, g_sp.sC>>>(frow, fcol, fval, dindex);
        cudaEventRecord(g_sp.evC, g_sp.sC);
    }

    cudaMemsetAsync(xp, 0, BB * NBANDS * HH * sizeof(float), 0);

    // CSR build: per-graph segmented hist+scan, then 200-block scatter
    build1_kernel<<<BB, 1024>>>(erow);

    if (par) {
        // dinv ready -> gemm1 (dinv epilogue) overlaps build2
        cudaEventRecord(g_sp.evD, 0);
        cudaStreamWaitEvent(g_sp.sB, g_sp.evD, 0);
        gemm64_kernel<<<(NN + 63) / 64, 256, 0, g_sp.sB>>>(x, W1, bufA, NN);
        cudaEventRecord(g_sp.evB, g_sp.sB);
    }

    build2_kernel<<<BB * NSEG, 1024>>>(erow, ecol);

    if (par) {
        cudaStreamWaitEvent(0, g_sp.evB, 0);   // join gemm1
    } else {
        gemm64_kernel<<<(NN + 63) / 64, 256>>>(x, W1, bufA, NN);
    }

    // GCN layer 1 aggregation
    agg_kernel<<<(NN * 32 + 255) / 256, 256>>>(bufA, bufB, b1);

    // GCN layer 2
    gemm64_kernel<<<(NN + 63) / 64, 256>>>(bufB, W2, bufA, NN);
    agg_kernel<<<(NN * 32 + 255) / 256, 256>>>(bufA, bufB, b2);

    if (par) {
        cudaStreamWaitEvent(0, g_sp.evC, 0);   // join framelet weights
    } else {
        frame_kernel<<<BB, 1024>>>(frow, fcol, fval, dindex);
    }

    // pool (200 blocks) + MLP head (50 blocks)
    pool_partial_kernel<<<BB * 4, 192>>>(bufB);
    head_kernel<<<BB, 64>>>(fcW1, fcb1, fcW2, fcb2, out);
}